// round 4
// baseline (speedup 1.0000x reference)
#include <cuda_runtime.h>
#include <cuda_bf16.h>
#include <math.h>

#define N_NODES 50000
#define N_EDGES 800000
#define FEAT    128
#define HEADS   8
#define CH      16

// ---------------- scratch (no allocs; referenced ONLY from device code) ----------
static __device__ __align__(16) float g_bufA[(size_t)N_NODES * FEAT];
static __device__ __align__(16) float g_bufB[(size_t)N_NODES * FEAT];
static __device__ float g_alsrc[N_NODES * HEADS];
static __device__ float g_aldst[N_NODES * HEADS];
static __device__ int   g_rowptr[N_NODES + 1];
static __device__ int   g_cnt[N_NODES];
static __device__ int   g_fill[N_NODES];
static __device__ int   g_col[N_EDGES];
static __device__ int   g_incl[N_NODES];
static __device__ int   g_bsum[64];
static __device__ float g_gsum[16];
static __device__ int   g_is64;

__device__ __forceinline__ float lrelu02(float x) { return x > 0.f ? x : 0.2f * x; }
__device__ __forceinline__ float elu1(float x)    { return x > 0.f ? x : (__expf(x) - 1.f); }
__device__ __forceinline__ int   clampN(int v)    { return v < 0 ? 0 : (v >= N_NODES ? N_NODES - 1 : v); }

// ---------------- edge dtype probe ----------------
// int64 edge ids (< 2^31, nonneg) -> every odd 32-bit word is 0.
__global__ void k_detect(const unsigned int* __restrict__ w) {
    __shared__ unsigned int sh[1024];
    int t = threadIdx.x;
    sh[t] = w[2 * t + 1];
    __syncthreads();
    for (int off = 512; off > 0; off >>= 1) {
        if (t < off) sh[t] |= sh[t + off];
        __syncthreads();
    }
    if (t == 0) g_is64 = (sh[0] == 0u) ? 1 : 0;
}

__device__ __forceinline__ int load_src(const void* eiv, int e) {
    return clampN(g_is64 ? (int)((const long long*)eiv)[e] : ((const int*)eiv)[e]);
}
__device__ __forceinline__ int load_dst(const void* eiv, int e) {
    return clampN(g_is64 ? (int)((const long long*)eiv)[N_EDGES + e]
                         : ((const int*)eiv)[N_EDGES + e]);
}

// ---------------- CSR build ----------------
__global__ void k_zero() {
    int i = blockIdx.x * blockDim.x + threadIdx.x;
    if (i < N_NODES) { g_cnt[i] = 0; g_fill[i] = 0; }
    if (i < 16) g_gsum[i] = 0.f;
}

__global__ void k_count(const void* __restrict__ eiv) {
    int e = blockIdx.x * blockDim.x + threadIdx.x;
    if (e >= N_EDGES) return;
    atomicAdd(&g_cnt[load_dst(eiv, e)], 1);
}

__global__ void k_scan1() {
    __shared__ int sh[1024];
    int t = threadIdx.x;
    int g = blockIdx.x * 1024 + t;
    int v = (g < N_NODES) ? g_cnt[g] : 0;
    sh[t] = v;
    __syncthreads();
    for (int off = 1; off < 1024; off <<= 1) {
        int add = (t >= off) ? sh[t - off] : 0;
        __syncthreads();
        sh[t] += add;
        __syncthreads();
    }
    if (g < N_NODES) g_incl[g] = sh[t];
    if (t == 1023) g_bsum[blockIdx.x] = sh[1023];
}

__global__ void k_scan2(int nchunks) {
    if (threadIdx.x == 0) {
        int acc = 0;
        for (int i = 0; i < nchunks; i++) { int v = g_bsum[i]; g_bsum[i] = acc; acc += v; }
    }
}

__global__ void k_scan3() {
    int i = blockIdx.x * blockDim.x + threadIdx.x;
    if (i >= N_NODES) return;
    g_rowptr[i + 1] = g_incl[i] + g_bsum[i >> 10];
    if (i == 0) g_rowptr[0] = 0;
}

__global__ void k_scatter(const void* __restrict__ eiv) {
    int e = blockIdx.x * blockDim.x + threadIdx.x;
    if (e >= N_EDGES) return;
    int d = load_dst(eiv, e);
    int pos = g_rowptr[d] + atomicAdd(&g_fill[d], 1);
    g_col[pos] = load_src(eiv, e);
}

// ---------------- SGEMM 128x128, BK=8, double-buffered ----------------
// g_bufA[M,128] = A[M,K] @ W[K,128].  SRC=0: A=Ain; SRC=1: A=g_bufB.
template <int SRC>
__global__ __launch_bounds__(256) void k_gemm(const float* __restrict__ Ain,
                                              const float* __restrict__ W,
                                              int M, int K) {
    const float* __restrict__ A = (SRC == 0) ? Ain : (const float*)g_bufB;
    float* __restrict__ C = g_bufA;

    __shared__ __align__(16) float As[2][8][128];  // [stage][k][m]
    __shared__ __align__(16) float Ws[2][8][128];  // [stage][k][n]

    const int tid  = threadIdx.x;
    const int row0 = blockIdx.x * 128;
    const int tx   = tid & 15;   // 0..15 -> n groups {tx*4, tx*4+64}
    const int ty   = tid >> 4;   // 0..15 -> m groups {ty*4, ty*4+64}

    // A-load mapping: 256 threads load 128x8 tile as two half-k slabs
    const int a_m = tid & 127;          // 0..127
    const int a_k = (tid >> 7) * 4;     // 0 or 4
    // W-load mapping: 8 rows x 128 cols
    const int w_k = tid >> 5;           // 0..7
    const int w_n = (tid & 31) * 4;     // 0..124

    float acc[2][2][4][4];
#pragma unroll
    for (int a = 0; a < 2; a++)
#pragma unroll
        for (int b = 0; b < 2; b++)
#pragma unroll
            for (int i = 0; i < 4; i++)
#pragma unroll
                for (int j = 0; j < 4; j++) acc[a][b][i][j] = 0.f;

    const int ar = row0 + a_m;
    const bool a_ok = (ar < M);
    const int nIter = K >> 3;

    // prologue: stage 0
    {
        float4 av = make_float4(0.f, 0.f, 0.f, 0.f);
        if (a_ok) av = *(const float4*)&A[(size_t)ar * K + a_k];
        As[0][a_k + 0][a_m] = av.x;
        As[0][a_k + 1][a_m] = av.y;
        As[0][a_k + 2][a_m] = av.z;
        As[0][a_k + 3][a_m] = av.w;
        float4 wv = *(const float4*)&W[(size_t)w_k * 128 + w_n];
        *(float4*)&Ws[0][w_k][w_n] = wv;
    }
    __syncthreads();

    for (int it = 0; it < nIter; it++) {
        const int cur = it & 1;
        const int nxt = cur ^ 1;
        float4 av, wv;
        const bool more = (it + 1 < nIter);
        if (more) {
            int k0 = (it + 1) << 3;
            av = make_float4(0.f, 0.f, 0.f, 0.f);
            if (a_ok) av = *(const float4*)&A[(size_t)ar * K + k0 + a_k];
            wv = *(const float4*)&W[(size_t)(k0 + w_k) * 128 + w_n];
        }
#pragma unroll
        for (int kk = 0; kk < 8; kk++) {
            float4 a0 = *(const float4*)&As[cur][kk][ty * 4];
            float4 a1 = *(const float4*)&As[cur][kk][ty * 4 + 64];
            float4 b0 = *(const float4*)&Ws[cur][kk][tx * 4];
            float4 b1 = *(const float4*)&Ws[cur][kk][tx * 4 + 64];
            const float am[2][4] = {{a0.x, a0.y, a0.z, a0.w}, {a1.x, a1.y, a1.z, a1.w}};
            const float bn[2][4] = {{b0.x, b0.y, b0.z, b0.w}, {b1.x, b1.y, b1.z, b1.w}};
#pragma unroll
            for (int mi = 0; mi < 2; mi++)
#pragma unroll
                for (int ni = 0; ni < 2; ni++)
#pragma unroll
                    for (int i = 0; i < 4; i++)
#pragma unroll
                        for (int j = 0; j < 4; j++)
                            acc[mi][ni][i][j] += am[mi][i] * bn[ni][j];
        }
        if (more) {
            As[nxt][a_k + 0][a_m] = av.x;
            As[nxt][a_k + 1][a_m] = av.y;
            As[nxt][a_k + 2][a_m] = av.z;
            As[nxt][a_k + 3][a_m] = av.w;
            *(float4*)&Ws[nxt][w_k][w_n] = wv;
        }
        __syncthreads();
    }

#pragma unroll
    for (int mi = 0; mi < 2; mi++)
#pragma unroll
        for (int i = 0; i < 4; i++) {
            int r = row0 + ty * 4 + i + mi * 64;
            if (r < M) {
#pragma unroll
                for (int ni = 0; ni < 2; ni++) {
                    float4 v = make_float4(acc[mi][ni][i][0], acc[mi][ni][i][1],
                                           acc[mi][ni][i][2], acc[mi][ni][i][3]);
                    *(float4*)&C[(size_t)r * 128 + tx * 4 + ni * 64] = v;
                }
            }
        }
}

// ---------------- attention logit projections (h = g_bufA) ----------------
__global__ void k_al(const float* __restrict__ a_src, const float* __restrict__ a_dst) {
    int t = blockIdx.x * blockDim.x + threadIdx.x;
    if (t >= N_NODES * HEADS) return;
    int n = t >> 3, j = t & 7;
    const float* hp = g_bufA + (size_t)n * FEAT + j * CH;
    const float* as = a_src + j * CH;
    const float* ad = a_dst + j * CH;
    float ss = 0.f, ds = 0.f;
#pragma unroll
    for (int c = 0; c < CH; c++) { float v = hp[c]; ss += v * as[c]; ds += v * ad[c]; }
    g_alsrc[t] = ss;
    g_aldst[t] = ds;
}

// ---------------- per-node softmax + aggregation (one warp / node), h = g_bufA ----
// MODE 0: g_bufB = elu(agg + bias)       (layers 1,2)
// MODE 1: outp[n*16+c] = mean_heads + b  (layer 3 -> d_out)
template <int MODE>
__global__ void k_agg(const float* __restrict__ bias, float* __restrict__ outp) {
    int gw = (blockIdx.x * blockDim.x + threadIdx.x) >> 5;
    if (gw >= N_NODES) return;
    int lane = threadIdx.x & 31;
    int d = gw;
    const float* __restrict__ h = g_bufA;
    float* __restrict__ out = (MODE == 0) ? (float*)g_bufB : outp;
    int beg = g_rowptr[d], end = g_rowptr[d + 1];

    float adst = 0.f, asrc_self = 0.f;
    if (lane < 8) {
        adst      = g_aldst[d * 8 + lane];
        asrc_self = g_alsrc[d * 8 + lane];
    }
    // pass 1: per-head max
    float m = 0.f;
    if (lane < 8) {
        m = lrelu02(asrc_self + adst);
        for (int i = beg; i < end; i++) {
            int s = g_col[i];
            m = fmaxf(m, lrelu02(g_alsrc[s * 8 + lane] + adst));
        }
    }
    // pass 2: denominator + weighted accumulation
    const int head = lane >> 2;
    float den = 0.f;
    float4 acc = make_float4(0.f, 0.f, 0.f, 0.f);
    {
        float p = 0.f;
        if (lane < 8) { p = __expf(lrelu02(asrc_self + adst) - m); den += p; }
        float w = __shfl_sync(0xffffffffu, p, head);
        float4 hv = *(const float4*)&h[(size_t)d * FEAT + lane * 4];
        acc.x += hv.x * w; acc.y += hv.y * w; acc.z += hv.z * w; acc.w += hv.w * w;
    }
    for (int i = beg; i < end; i++) {
        int s = g_col[i];
        float p = 0.f;
        if (lane < 8) { p = __expf(lrelu02(g_alsrc[s * 8 + lane] + adst) - m); den += p; }
        float w = __shfl_sync(0xffffffffu, p, head);
        float4 hv = *(const float4*)&h[(size_t)s * FEAT + lane * 4];
        acc.x += hv.x * w; acc.y += hv.y * w; acc.z += hv.z * w; acc.w += hv.w * w;
    }
    float denw = __shfl_sync(0xffffffffu, den, head);
    float inv = 1.f / denw;
    acc.x *= inv; acc.y *= inv; acc.z *= inv; acc.w *= inv;

    if (MODE == 0) {
        float4 bb = *(const float4*)&bias[lane * 4];
        acc.x = elu1(acc.x + bb.x);
        acc.y = elu1(acc.y + bb.y);
        acc.z = elu1(acc.z + bb.z);
        acc.w = elu1(acc.w + bb.w);
        *(float4*)&out[(size_t)d * FEAT + lane * 4] = acc;
    } else {
#pragma unroll
        for (int off = 4; off <= 16; off <<= 1) {
            acc.x += __shfl_xor_sync(0xffffffffu, acc.x, off);
            acc.y += __shfl_xor_sync(0xffffffffu, acc.y, off);
            acc.z += __shfl_xor_sync(0xffffffffu, acc.z, off);
            acc.w += __shfl_xor_sync(0xffffffffu, acc.w, off);
        }
        if (lane < 4) {
            float4 bb = *(const float4*)&bias[lane * 4];
            float4 r;
            r.x = acc.x * 0.125f + bb.x;
            r.y = acc.y * 0.125f + bb.y;
            r.z = acc.z * 0.125f + bb.z;
            r.w = acc.w * 0.125f + bb.w;
            *(float4*)&out[(size_t)d * CH + lane * 4] = r;
        }
    }
}

// ---------------- anomaly head ----------------
__global__ void k_anomaly(const float* __restrict__ w1, const float* __restrict__ b1,
                          const float* __restrict__ w2, const float* __restrict__ b2,
                          float* __restrict__ out) {
    int n = blockIdx.x * blockDim.x + threadIdx.x;
    if (n >= N_NODES) return;
    float hv[16];
#pragma unroll
    for (int c = 0; c < 16; c++) hv[c] = out[(size_t)n * 16 + c];
    float acc = b2[0];
#pragma unroll
    for (int u = 0; u < 32; u++) {
        float t = b1[u];
#pragma unroll
        for (int c = 0; c < 16; c++) t += hv[c] * w1[c * 32 + u];
        acc += fmaxf(t, 0.f) * w2[u];
    }
    out[800000 + n] = 1.f / (1.f + __expf(-acc));
}

// ---------------- graph mean ----------------
__global__ void k_gsum(const float* __restrict__ hout) {
    __shared__ float sh[256];
    int tid = threadIdx.x;
    float s = 0.f;
    size_t total = (size_t)N_NODES * 16;
    size_t stride = (size_t)gridDim.x * 256;
    for (size_t idx = (size_t)blockIdx.x * 256 + tid; idx < total; idx += stride)
        s += hout[idx];
    sh[tid] = s;
    __syncthreads();
    for (int off = 128; off >= 16; off >>= 1) {
        if (tid < off) sh[tid] += sh[tid + off];
        __syncthreads();
    }
    if (tid < 16) atomicAdd(&g_gsum[tid], sh[tid]);
}

// ---------------- graph classifier ----------------
__global__ void k_final(const float* __restrict__ w1, const float* __restrict__ b1,
                        const float* __restrict__ w2, const float* __restrict__ b2,
                        float* __restrict__ out) {
    __shared__ float emb[16];
    __shared__ float hid[64];
    int t = threadIdx.x;
    if (t < 16) {
        float e = g_gsum[t] * (1.f / (float)N_NODES);
        emb[t] = e;
        out[850000 + t] = e;
    }
    __syncthreads();
    float s = b1[t];
#pragma unroll
    for (int c = 0; c < 16; c++) s += emb[c] * w1[c * 64 + t];
    hid[t] = fmaxf(s, 0.f);
    __syncthreads();
    if (t < 2) {
        float r = b2[t];
#pragma unroll
        for (int u = 0; u < 64; u++) r += hid[u] * w2[u * 2 + t];
        out[850016 + t] = r;
    }
}

// ---------------- launch ----------------
extern "C" void kernel_launch(void* const* d_in, const int* in_sizes, int n_in,
                              void* d_out, int out_size) {
    const float* x      = (const float*)d_in[0];
    const void*  ei     = d_in[1];
    const float* W1     = (const float*)d_in[2];
    const float* a1s    = (const float*)d_in[3];
    const float* a1d    = (const float*)d_in[4];
    const float* b1     = (const float*)d_in[5];
    const float* W2     = (const float*)d_in[6];
    const float* a2s    = (const float*)d_in[7];
    const float* a2d    = (const float*)d_in[8];
    const float* b2     = (const float*)d_in[9];
    const float* W3     = (const float*)d_in[10];
    const float* a3s    = (const float*)d_in[11];
    const float* a3d    = (const float*)d_in[12];
    const float* b3     = (const float*)d_in[13];
    const float* cls_w1 = (const float*)d_in[14];
    const float* cls_b1 = (const float*)d_in[15];
    const float* cls_w2 = (const float*)d_in[16];
    const float* cls_b2 = (const float*)d_in[17];
    const float* an_w1  = (const float*)d_in[18];
    const float* an_b1  = (const float*)d_in[19];
    const float* an_w2  = (const float*)d_in[20];
    const float* an_b2  = (const float*)d_in[21];
    float* out = (float*)d_out;

    const int TB = 256;
    const int nodeBlocks = (N_NODES + TB - 1) / TB;
    const int edgeBlocks = (N_EDGES + TB - 1) / TB;
    const int alBlocks   = (N_NODES * HEADS + TB - 1) / TB;
    const int aggBlocks  = (N_NODES * 32 + TB - 1) / TB;
    const int gemmBlocks = (N_NODES + 127) / 128;  // 391
    const int nchunks    = (N_NODES + 1023) / 1024;

    // CSR by destination
    k_detect<<<1, 1024>>>((const unsigned int*)ei);
    k_zero<<<nodeBlocks, TB>>>();
    k_count<<<edgeBlocks, TB>>>(ei);
    k_scan1<<<nchunks, 1024>>>();
    k_scan2<<<1, 32>>>(nchunks);
    k_scan3<<<nodeBlocks, TB>>>();
    k_scatter<<<edgeBlocks, TB>>>(ei);

    // layer 1
    k_gemm<0><<<gemmBlocks, TB>>>(x, W1, N_NODES, 256);
    k_al<<<alBlocks, TB>>>(a1s, a1d);
    k_agg<0><<<aggBlocks, TB>>>(b1, nullptr);

    // layer 2
    k_gemm<1><<<gemmBlocks, TB>>>(nullptr, W2, N_NODES, 128);
    k_al<<<alBlocks, TB>>>(a2s, a2d);
    k_agg<0><<<aggBlocks, TB>>>(b2, nullptr);

    // layer 3
    k_gemm<1><<<gemmBlocks, TB>>>(nullptr, W3, N_NODES, 128);
    k_al<<<alBlocks, TB>>>(a3s, a3d);
    k_agg<1><<<aggBlocks, TB>>>(b3, out);

    // heads
    k_anomaly<<<nodeBlocks, TB>>>(an_w1, an_b1, an_w2, an_b2, out);
    k_gsum<<<64, TB>>>(out);
    k_final<<<1, 64>>>(cls_w1, cls_b1, cls_w2, cls_b2, out);
}

// round 5
// speedup vs baseline: 1.2129x; 1.2129x over previous
#include <cuda_runtime.h>
#include <cuda_bf16.h>
#include <math.h>

#define N_NODES 50000
#define N_EDGES 800000
#define FEAT    128
#define HEADS   8
#define CH      16

// ---------------- scratch (no allocs; referenced ONLY from device code) ----------
static __device__ __align__(16) float g_bufA[(size_t)N_NODES * FEAT];
static __device__ __align__(16) float g_bufB[(size_t)N_NODES * FEAT];
static __device__ float g_alsrc[N_NODES * HEADS];
static __device__ float g_aldst[N_NODES * HEADS];
static __device__ int   g_rowptr[N_NODES + 1];
static __device__ int   g_cnt[N_NODES];
static __device__ int   g_fill[N_NODES];
static __device__ int   g_col[N_EDGES];
static __device__ int   g_incl[N_NODES];
static __device__ int   g_bsum[64];
static __device__ float g_gsum[16];
static __device__ int   g_is64;

__device__ __forceinline__ float lrelu02(float x) { return x > 0.f ? x : 0.2f * x; }
__device__ __forceinline__ float elu1(float x)    { return x > 0.f ? x : (__expf(x) - 1.f); }
__device__ __forceinline__ int   clampN(int v)    { return v < 0 ? 0 : (v >= N_NODES ? N_NODES - 1 : v); }

// ---------------- edge dtype probe ----------------
__global__ void k_detect(const unsigned int* __restrict__ w) {
    __shared__ unsigned int sh[1024];
    int t = threadIdx.x;
    sh[t] = w[2 * t + 1];
    __syncthreads();
    for (int off = 512; off > 0; off >>= 1) {
        if (t < off) sh[t] |= sh[t + off];
        __syncthreads();
    }
    if (t == 0) g_is64 = (sh[0] == 0u) ? 1 : 0;
}

__device__ __forceinline__ int load_src(const void* eiv, int e) {
    return clampN(g_is64 ? (int)((const long long*)eiv)[e] : ((const int*)eiv)[e]);
}
__device__ __forceinline__ int load_dst(const void* eiv, int e) {
    return clampN(g_is64 ? (int)((const long long*)eiv)[N_EDGES + e]
                         : ((const int*)eiv)[N_EDGES + e]);
}

// ---------------- CSR build ----------------
__global__ void k_zero() {
    int i = blockIdx.x * blockDim.x + threadIdx.x;
    if (i < N_NODES) { g_cnt[i] = 0; g_fill[i] = 0; }
    if (i < 16) g_gsum[i] = 0.f;
}

__global__ void k_count(const void* __restrict__ eiv) {
    int e = blockIdx.x * blockDim.x + threadIdx.x;
    if (e >= N_EDGES) return;
    atomicAdd(&g_cnt[load_dst(eiv, e)], 1);
}

__global__ void k_scan1() {
    __shared__ int sh[1024];
    int t = threadIdx.x;
    int g = blockIdx.x * 1024 + t;
    int v = (g < N_NODES) ? g_cnt[g] : 0;
    sh[t] = v;
    __syncthreads();
    for (int off = 1; off < 1024; off <<= 1) {
        int add = (t >= off) ? sh[t - off] : 0;
        __syncthreads();
        sh[t] += add;
        __syncthreads();
    }
    if (g < N_NODES) g_incl[g] = sh[t];
    if (t == 1023) g_bsum[blockIdx.x] = sh[1023];
}

__global__ void k_scan2(int nchunks) {
    if (threadIdx.x == 0) {
        int acc = 0;
        for (int i = 0; i < nchunks; i++) { int v = g_bsum[i]; g_bsum[i] = acc; acc += v; }
    }
}

__global__ void k_scan3() {
    int i = blockIdx.x * blockDim.x + threadIdx.x;
    if (i >= N_NODES) return;
    g_rowptr[i + 1] = g_incl[i] + g_bsum[i >> 10];
    if (i == 0) g_rowptr[0] = 0;
}

__global__ void k_scatter(const void* __restrict__ eiv) {
    int e = blockIdx.x * blockDim.x + threadIdx.x;
    if (e >= N_EDGES) return;
    int d = load_dst(eiv, e);
    int pos = g_rowptr[d] + atomicAdd(&g_fill[d], 1);
    g_col[pos] = load_src(eiv, e);
}

// ---------------- fused SGEMM + attention-logit epilogue ----------------
// g_bufA[M,128] = A[M,K] @ W[K,128]; also writes g_alsrc/g_aldst per (row,head).
// BM=64, BK=16, 256 threads, 8x4 microtile, reg-prefetched global loads.
// SRC=0: A = Ain (input x); SRC=1: A = g_bufB.
template <int SRC>
__global__ __launch_bounds__(256) void k_gemm(const float* __restrict__ Ain,
                                              const float* __restrict__ W,
                                              const float* __restrict__ a_src,
                                              const float* __restrict__ a_dst,
                                              int M, int K) {
    const float* __restrict__ A = (SRC == 0) ? Ain : (const float*)g_bufB;
    float* __restrict__ C = g_bufA;

    __shared__ __align__(16) float As[16][65];
    __shared__ __align__(16) float Ws[16][128];
    const int tid = threadIdx.x;
    const int tr  = tid >> 5;   // 0..7  (row group of 8)
    const int tc  = tid & 31;   // 0..31 (col group of 4)
    const int row0 = blockIdx.x * 64;

    float acc[8][4];
#pragma unroll
    for (int i = 0; i < 8; i++)
#pragma unroll
        for (int j = 0; j < 4; j++) acc[i][j] = 0.f;

    const int la_row = tid >> 2;        // 0..63
    const int la_k   = (tid & 3) * 4;   // 0,4,8,12
    const int w_r0   = tid >> 5;        // 0..7   (two slabs: +8)
    const int w_c    = (tid & 31) * 4;

    const int ar = row0 + la_row;
    const bool a_ok = (ar < M);
    const int nIter = K >> 4;

    // prologue: prefetch tile 0 into regs
    float4 av = make_float4(0.f, 0.f, 0.f, 0.f);
    if (a_ok) av = *(const float4*)&A[(size_t)ar * K + la_k];
    float4 wv0 = *(const float4*)&W[(size_t)w_r0 * 128 + w_c];
    float4 wv1 = *(const float4*)&W[(size_t)(w_r0 + 8) * 128 + w_c];

    for (int it = 0; it < nIter; it++) {
        // stage regs -> smem
        As[la_k + 0][la_row] = av.x;
        As[la_k + 1][la_row] = av.y;
        As[la_k + 2][la_row] = av.z;
        As[la_k + 3][la_row] = av.w;
        *(float4*)&Ws[w_r0][w_c]     = wv0;
        *(float4*)&Ws[w_r0 + 8][w_c] = wv1;
        __syncthreads();

        // prefetch next tile while computing this one
        if (it + 1 < nIter) {
            int k0 = (it + 1) << 4;
            av = make_float4(0.f, 0.f, 0.f, 0.f);
            if (a_ok) av = *(const float4*)&A[(size_t)ar * K + k0 + la_k];
            wv0 = *(const float4*)&W[(size_t)(k0 + w_r0) * 128 + w_c];
            wv1 = *(const float4*)&W[(size_t)(k0 + w_r0 + 8) * 128 + w_c];
        }
#pragma unroll
        for (int kk = 0; kk < 16; kk++) {
            float a[8];
#pragma unroll
            for (int i = 0; i < 8; i++) a[i] = As[kk][tr * 8 + i];
            float4 b = *(const float4*)&Ws[kk][tc * 4];
#pragma unroll
            for (int i = 0; i < 8; i++) {
                acc[i][0] += a[i] * b.x;
                acc[i][1] += a[i] * b.y;
                acc[i][2] += a[i] * b.z;
                acc[i][3] += a[i] * b.w;
            }
        }
        __syncthreads();
    }

    // write C
#pragma unroll
    for (int i = 0; i < 8; i++) {
        int r = row0 + tr * 8 + i;
        if (r < M) {
            float4 v = make_float4(acc[i][0], acc[i][1], acc[i][2], acc[i][3]);
            *(float4*)&C[(size_t)r * 128 + tc * 4] = v;
        }
    }

    // fused attention logits: head = tc/4, 4 lanes per head, shfl-reduce
    const int head = tc >> 2;
    const int cofs = (tc & 3) * 4;
    float asv[4], adv[4];
#pragma unroll
    for (int j = 0; j < 4; j++) {
        asv[j] = a_src[head * CH + cofs + j];
        adv[j] = a_dst[head * CH + cofs + j];
    }
#pragma unroll
    for (int i = 0; i < 8; i++) {
        float ss = acc[i][0] * asv[0] + acc[i][1] * asv[1] +
                   acc[i][2] * asv[2] + acc[i][3] * asv[3];
        float ds = acc[i][0] * adv[0] + acc[i][1] * adv[1] +
                   acc[i][2] * adv[2] + acc[i][3] * adv[3];
        ss += __shfl_xor_sync(0xffffffffu, ss, 1);
        ss += __shfl_xor_sync(0xffffffffu, ss, 2);
        ds += __shfl_xor_sync(0xffffffffu, ds, 1);
        ds += __shfl_xor_sync(0xffffffffu, ds, 2);
        if ((tc & 3) == 0) {
            int r = row0 + tr * 8 + i;
            if (r < M) {
                g_alsrc[r * 8 + head] = ss;
                g_aldst[r * 8 + head] = ds;
            }
        }
    }
}

// ---------------- per-node softmax + aggregation (one warp / node) ----------------
// Softmax without max-shift (shift-invariant; logits bounded far below fp32 overflow).
// MODE 0: g_bufB = elu(agg + bias)       (layers 1,2)
// MODE 1: outp[n*16+c] = mean_heads + b  (layer 3 -> d_out)
template <int MODE>
__global__ void k_agg(const float* __restrict__ bias, float* __restrict__ outp) {
    int gw = (blockIdx.x * blockDim.x + threadIdx.x) >> 5;
    if (gw >= N_NODES) return;
    int lane = threadIdx.x & 31;
    int d = gw;
    const float* __restrict__ h = g_bufA;
    float* __restrict__ out = (MODE == 0) ? (float*)g_bufB : outp;
    int beg = g_rowptr[d], end = g_rowptr[d + 1];

    float adst = 0.f, asrc_self = 0.f;
    if (lane < 8) {
        adst      = g_aldst[d * 8 + lane];
        asrc_self = g_alsrc[d * 8 + lane];
    }
    const int head = lane >> 2;  // lane l owns channels 4l..4l+3 -> head l/4
    float den = 0.f;
    float4 acc = make_float4(0.f, 0.f, 0.f, 0.f);
    {   // self loop
        float p = 0.f;
        if (lane < 8) { p = __expf(lrelu02(asrc_self + adst)); den += p; }
        float w = __shfl_sync(0xffffffffu, p, head);
        float4 hv = *(const float4*)&h[(size_t)d * FEAT + lane * 4];
        acc.x += hv.x * w; acc.y += hv.y * w; acc.z += hv.z * w; acc.w += hv.w * w;
    }
    for (int i = beg; i < end; i++) {
        int s = g_col[i];
        float p = 0.f;
        if (lane < 8) { p = __expf(lrelu02(g_alsrc[s * 8 + lane] + adst)); den += p; }
        float w = __shfl_sync(0xffffffffu, p, head);
        float4 hv = *(const float4*)&h[(size_t)s * FEAT + lane * 4];
        acc.x += hv.x * w; acc.y += hv.y * w; acc.z += hv.z * w; acc.w += hv.w * w;
    }
    float denw = __shfl_sync(0xffffffffu, den, head);
    float inv = 1.f / denw;
    acc.x *= inv; acc.y *= inv; acc.z *= inv; acc.w *= inv;

    if (MODE == 0) {
        float4 bb = *(const float4*)&bias[lane * 4];
        acc.x = elu1(acc.x + bb.x);
        acc.y = elu1(acc.y + bb.y);
        acc.z = elu1(acc.z + bb.z);
        acc.w = elu1(acc.w + bb.w);
        *(float4*)&out[(size_t)d * FEAT + lane * 4] = acc;
    } else {
#pragma unroll
        for (int off = 4; off <= 16; off <<= 1) {
            acc.x += __shfl_xor_sync(0xffffffffu, acc.x, off);
            acc.y += __shfl_xor_sync(0xffffffffu, acc.y, off);
            acc.z += __shfl_xor_sync(0xffffffffu, acc.z, off);
            acc.w += __shfl_xor_sync(0xffffffffu, acc.w, off);
        }
        if (lane < 4) {
            float4 bb = *(const float4*)&bias[lane * 4];
            float4 r;
            r.x = acc.x * 0.125f + bb.x;
            r.y = acc.y * 0.125f + bb.y;
            r.z = acc.z * 0.125f + bb.z;
            r.w = acc.w * 0.125f + bb.w;
            *(float4*)&out[(size_t)d * CH + lane * 4] = r;
        }
    }
}

// ---------------- anomaly head ----------------
__global__ void k_anomaly(const float* __restrict__ w1, const float* __restrict__ b1,
                          const float* __restrict__ w2, const float* __restrict__ b2,
                          float* __restrict__ out) {
    int n = blockIdx.x * blockDim.x + threadIdx.x;
    if (n >= N_NODES) return;
    float hv[16];
#pragma unroll
    for (int c = 0; c < 16; c++) hv[c] = out[(size_t)n * 16 + c];
    float acc = b2[0];
#pragma unroll
    for (int u = 0; u < 32; u++) {
        float t = b1[u];
#pragma unroll
        for (int c = 0; c < 16; c++) t += hv[c] * w1[c * 32 + u];
        acc += fmaxf(t, 0.f) * w2[u];
    }
    out[800000 + n] = 1.f / (1.f + __expf(-acc));
}

// ---------------- graph mean ----------------
__global__ void k_gsum(const float* __restrict__ hout) {
    __shared__ float sh[256];
    int tid = threadIdx.x;
    float s = 0.f;
    size_t total = (size_t)N_NODES * 16;
    size_t stride = (size_t)gridDim.x * 256;
    for (size_t idx = (size_t)blockIdx.x * 256 + tid; idx < total; idx += stride)
        s += hout[idx];
    sh[tid] = s;
    __syncthreads();
    for (int off = 128; off >= 16; off >>= 1) {
        if (tid < off) sh[tid] += sh[tid + off];
        __syncthreads();
    }
    if (tid < 16) atomicAdd(&g_gsum[tid], sh[tid]);
}

// ---------------- graph classifier ----------------
__global__ void k_final(const float* __restrict__ w1, const float* __restrict__ b1,
                        const float* __restrict__ w2, const float* __restrict__ b2,
                        float* __restrict__ out) {
    __shared__ float emb[16];
    __shared__ float hid[64];
    int t = threadIdx.x;
    if (t < 16) {
        float e = g_gsum[t] * (1.f / (float)N_NODES);
        emb[t] = e;
        out[850000 + t] = e;
    }
    __syncthreads();
    float s = b1[t];
#pragma unroll
    for (int c = 0; c < 16; c++) s += emb[c] * w1[c * 64 + t];
    hid[t] = fmaxf(s, 0.f);
    __syncthreads();
    if (t < 2) {
        float r = b2[t];
#pragma unroll
        for (int u = 0; u < 64; u++) r += hid[u] * w2[u * 2 + t];
        out[850016 + t] = r;
    }
}

// ---------------- launch ----------------
extern "C" void kernel_launch(void* const* d_in, const int* in_sizes, int n_in,
                              void* d_out, int out_size) {
    const float* x      = (const float*)d_in[0];
    const void*  ei     = d_in[1];
    const float* W1     = (const float*)d_in[2];
    const float* a1s    = (const float*)d_in[3];
    const float* a1d    = (const float*)d_in[4];
    const float* b1     = (const float*)d_in[5];
    const float* W2     = (const float*)d_in[6];
    const float* a2s    = (const float*)d_in[7];
    const float* a2d    = (const float*)d_in[8];
    const float* b2     = (const float*)d_in[9];
    const float* W3     = (const float*)d_in[10];
    const float* a3s    = (const float*)d_in[11];
    const float* a3d    = (const float*)d_in[12];
    const float* b3     = (const float*)d_in[13];
    const float* cls_w1 = (const float*)d_in[14];
    const float* cls_b1 = (const float*)d_in[15];
    const float* cls_w2 = (const float*)d_in[16];
    const float* cls_b2 = (const float*)d_in[17];
    const float* an_w1  = (const float*)d_in[18];
    const float* an_b1  = (const float*)d_in[19];
    const float* an_w2  = (const float*)d_in[20];
    const float* an_b2  = (const float*)d_in[21];
    float* out = (float*)d_out;

    const int TB = 256;
    const int nodeBlocks = (N_NODES + TB - 1) / TB;
    const int edgeBlocks = (N_EDGES + TB - 1) / TB;
    const int aggBlocks  = (N_NODES * 32 + TB - 1) / TB;
    const int gemmBlocks = (N_NODES + 63) / 64;   // 782
    const int nchunks    = (N_NODES + 1023) / 1024;

    // CSR by destination
    k_detect<<<1, 1024>>>((const unsigned int*)ei);
    k_zero<<<nodeBlocks, TB>>>();
    k_count<<<edgeBlocks, TB>>>(ei);
    k_scan1<<<nchunks, 1024>>>();
    k_scan2<<<1, 32>>>(nchunks);
    k_scan3<<<nodeBlocks, TB>>>();
    k_scatter<<<edgeBlocks, TB>>>(ei);

    // layer 1 (GEMM + fused logits)
    k_gemm<0><<<gemmBlocks, TB>>>(x, W1, a1s, a1d, N_NODES, 256);
    k_agg<0><<<aggBlocks, TB>>>(b1, nullptr);

    // layer 2
    k_gemm<1><<<gemmBlocks, TB>>>(nullptr, W2, a2s, a2d, N_NODES, 128);
    k_agg<0><<<aggBlocks, TB>>>(b2, nullptr);

    // layer 3
    k_gemm<1><<<gemmBlocks, TB>>>(nullptr, W3, a3s, a3d, N_NODES, 128);
    k_agg<1><<<aggBlocks, TB>>>(b3, out);

    // heads
    k_anomaly<<<nodeBlocks, TB>>>(an_w1, an_b1, an_w2, an_b2, out);
    k_gsum<<<64, TB>>>(out);
    k_final<<<1, 64>>>(cls_w1, cls_b1, cls_w2, cls_b2, out);
}